// round 8
// baseline (speedup 1.0000x reference)
#include <cuda_runtime.h>
#include <math.h>
#include <stdint.h>

// Problem constants
#define NB   4
#define LL   4096
#define SS   256
#define HH   256
#define FCn  8
#define SCn  32
#define MM   32      // NB*FCn
#define H2   512
#define KK   256     // inner dim of dense GEMMs

typedef unsigned long long u64;

// Scratch (device globals; no dynamic allocation allowed)
__device__ float    g_c1[NB * SS * H2];       // center1 @ W1^T + b1
__device__ uint32_t g_cpHi[MM * SS * SCn];    // tf32 of normalized c_point
__device__ float    g_cpF [MM * SS * SCn];    // fp32 normalized c_point
__device__ float    g_cv  [MM * SS * SCn];    // c_value
__device__ float    g_x0p [NB * LL * HH];     // x0 @ W0^T + b0
__device__ float    g_disp[NB * LL * HH];     // dispatched

// ---------------------------------------------------------------------------
// PTX helpers
// ---------------------------------------------------------------------------
__device__ __forceinline__ u64 ffma2(u64 a, u64 b, u64 c) {
    u64 d;
    asm("fma.rn.f32x2 %0, %1, %2, %3;" : "=l"(d) : "l"(a), "l"(b), "l"(c));
    return d;
}
__device__ __forceinline__ u64 pack2(float x, float y) {
    u64 r;
    asm("mov.b64 %0, {%1, %2};" : "=l"(r) : "f"(x), "f"(y));
    return r;
}
__device__ __forceinline__ float2 unpack2(u64 v) {
    float2 f;
    asm("mov.b64 {%0, %1}, %2;" : "=f"(f.x), "=f"(f.y) : "l"(v));
    return f;
}
__device__ __forceinline__ uint32_t f2tf32(float x) {
    uint32_t r;
    asm("cvt.rna.tf32.f32 %0, %1;" : "=r"(r) : "f"(x));
    return r;
}
// m16n8k8 tf32 warp MMA, D += A*B (fp32 accum)
__device__ __forceinline__ void mma8(float4& d, const uint32_t* a, const uint32_t* b) {
    asm("mma.sync.aligned.m16n8k8.row.col.f32.tf32.tf32.f32 "
        "{%0,%1,%2,%3}, {%4,%5,%6,%7}, {%8,%9}, {%0,%1,%2,%3};"
        : "+f"(d.x), "+f"(d.y), "+f"(d.z), "+f"(d.w)
        : "r"(a[0]), "r"(a[1]), "r"(a[2]), "r"(a[3]), "r"(b[0]), "r"(b[1]));
}

// ---------------------------------------------------------------------------
// Tensor-core GEMM via mma.sync tf32:
//   C[R][Hout] = A[R][256] @ B[Hout][256]^T + bias
// NPASS=1: plain tf32 — K4.  NPASS=3: hi/lo compensation (~fp32) — K2.
// ---------------------------------------------------------------------------
template<int NPASS>
__global__ __launch_bounds__(256, 2) void gemm_mma(
    const float* __restrict__ A, const float* __restrict__ B,
    const float* __restrict__ bias, float* __restrict__ C, int Hout)
{
    extern __shared__ __align__(16) uint32_t msm[];
    uint32_t* Ah = msm;                                   // [128][36]
    uint32_t* Al = Ah + 4608;                             // NPASS==3 only
    uint32_t* Bh = (NPASS == 3) ? (Al + 4608) : (Ah + 4608);  // [64][36]
    uint32_t* Bl = Bh + 2304;                             // NPASS==3 only

    const int tid  = threadIdx.x;
    const int wid  = tid >> 5;
    const int lane = tid & 31;
    const int g  = lane >> 2;
    const int tg = lane & 3;
    const int mbase = (wid & 3) * 32;
    const int nbase = (wid >> 2) * 32;
    const int r0 = blockIdx.x * 128;
    const int h0 = blockIdx.y * 64;

    float4 acc[2][4];
    #pragma unroll
    for (int i = 0; i < 2; i++)
        #pragma unroll
        for (int j = 0; j < 4; j++) acc[i][j] = make_float4(0.f, 0.f, 0.f, 0.f);

    for (int c = 0; c < 8; c++) {
        __syncthreads();
        #pragma unroll
        for (int it = 0; it < 4; it++) {
            int idx = tid + it * 256;
            int row = idx >> 3, j = idx & 7;
            float4 v = *(const float4*)&A[(size_t)(r0 + row) * 256 + c * 32 + j * 4];
            uint32_t base = row * 36 + j * 4;
            float xs[4] = {v.x, v.y, v.z, v.w};
            #pragma unroll
            for (int t = 0; t < 4; t++) {
                uint32_t hi = f2tf32(xs[t]);
                Ah[base + t] = hi;
                if constexpr (NPASS == 3)
                    Al[base + t] = f2tf32(xs[t] - __uint_as_float(hi));
            }
        }
        #pragma unroll
        for (int it = 0; it < 2; it++) {
            int idx = tid + it * 256;
            int row = idx >> 3, j = idx & 7;
            float4 v = *(const float4*)&B[(size_t)(h0 + row) * 256 + c * 32 + j * 4];
            uint32_t base = row * 36 + j * 4;
            float xs[4] = {v.x, v.y, v.z, v.w};
            #pragma unroll
            for (int t = 0; t < 4; t++) {
                uint32_t hi = f2tf32(xs[t]);
                Bh[base + t] = hi;
                if constexpr (NPASS == 3)
                    Bl[base + t] = f2tf32(xs[t] - __uint_as_float(hi));
            }
        }
        __syncthreads();

        #pragma unroll
        for (int ks = 0; ks < 4; ks++) {
            const int k0 = ks * 8;
            uint32_t ah[2][4], bh[4][2];
            #pragma unroll
            for (int i = 0; i < 2; i++) {
                uint32_t rb = (mbase + i * 16 + g) * 36 + k0 + tg;
                ah[i][0] = Ah[rb];
                ah[i][1] = Ah[rb + 8 * 36];
                ah[i][2] = Ah[rb + 4];
                ah[i][3] = Ah[rb + 8 * 36 + 4];
            }
            #pragma unroll
            for (int j = 0; j < 4; j++) {
                uint32_t rb = (nbase + j * 8 + g) * 36 + k0 + tg;
                bh[j][0] = Bh[rb];
                bh[j][1] = Bh[rb + 4];
            }
            #pragma unroll
            for (int i = 0; i < 2; i++)
                #pragma unroll
                for (int j = 0; j < 4; j++)
                    mma8(acc[i][j], ah[i], bh[j]);

            if constexpr (NPASS == 3) {
                uint32_t bl[4][2];
                #pragma unroll
                for (int j = 0; j < 4; j++) {
                    uint32_t rb = (nbase + j * 8 + g) * 36 + k0 + tg;
                    bl[j][0] = Bl[rb];
                    bl[j][1] = Bl[rb + 4];
                }
                #pragma unroll
                for (int i = 0; i < 2; i++)
                    #pragma unroll
                    for (int j = 0; j < 4; j++)
                        mma8(acc[i][j], ah[i], bl[j]);
                uint32_t al[2][4];
                #pragma unroll
                for (int i = 0; i < 2; i++) {
                    uint32_t rb = (mbase + i * 16 + g) * 36 + k0 + tg;
                    al[i][0] = Al[rb];
                    al[i][1] = Al[rb + 8 * 36];
                    al[i][2] = Al[rb + 4];
                    al[i][3] = Al[rb + 8 * 36 + 4];
                }
                #pragma unroll
                for (int i = 0; i < 2; i++)
                    #pragma unroll
                    for (int j = 0; j < 4; j++)
                        mma8(acc[i][j], al[i], bh[j]);
            }
        }
    }

    #pragma unroll
    for (int j = 0; j < 4; j++) {
        int col = h0 + nbase + j * 8 + 2 * tg;
        float2 bb = *(const float2*)&bias[col];
        #pragma unroll
        for (int i = 0; i < 2; i++) {
            int row = r0 + mbase + i * 16 + g;
            float2 o0 = make_float2(acc[i][j].x + bb.x, acc[i][j].y + bb.y);
            float2 o1 = make_float2(acc[i][j].z + bb.x, acc[i][j].w + bb.y);
            *(float2*)&C[(size_t)row * Hout + col] = o0;
            *(float2*)&C[(size_t)(row + 8) * Hout + col] = o1;
        }
    }
}

// ---------------------------------------------------------------------------
// Dense fp32 GEMM (K1 only)
// ---------------------------------------------------------------------------
template<int NT>
__global__ __launch_bounds__(256, 2) void gemm_nt(
    const float* __restrict__ A, const float* __restrict__ B,
    const float* __restrict__ bias, float* __restrict__ C, int Hout)
{
    constexpr int SN = NT / 16;
    __shared__ __align__(16) float as[32][132];
    __shared__ __align__(16) float bs[32][NT + 4];

    const int r0 = blockIdx.x * 128;
    const int h0 = blockIdx.y * NT;
    const int tid = threadIdx.x;
    const int tc = tid & 15;
    const int tr = tid >> 4;
    const int k4 = (tid & 7) * 4;
    const int rl = tid >> 3;

    u64 acc[4][SN];
    #pragma unroll
    for (int p = 0; p < 4; p++)
        #pragma unroll
        for (int j = 0; j < SN; j++) acc[p][j] = 0ull;

    for (int k0 = 0; k0 < KK; k0 += 32) {
        #pragma unroll
        for (int it = 0; it < 4; it++) {
            int row = rl + it * 32;
            float4 v = *(const float4*)&A[(size_t)(r0 + row) * KK + k0 + k4];
            as[k4 + 0][row] = v.x;
            as[k4 + 1][row] = v.y;
            as[k4 + 2][row] = v.z;
            as[k4 + 3][row] = v.w;
        }
        #pragma unroll
        for (int it = 0; it < NT / 32; it++) {
            int h = rl + it * 32;
            float4 v = *(const float4*)&B[(size_t)(h0 + h) * KK + k0 + k4];
            bs[k4 + 0][h] = v.x;
            bs[k4 + 1][h] = v.y;
            bs[k4 + 2][h] = v.z;
            bs[k4 + 3][h] = v.w;
        }
        __syncthreads();

        #pragma unroll 8
        for (int kk = 0; kk < 32; kk++) {
            ulonglong2 a01 = *(const ulonglong2*)&as[kk][tr * 8];
            ulonglong2 a23 = *(const ulonglong2*)&as[kk][tr * 8 + 4];
            u64 ap[4] = {a01.x, a01.y, a23.x, a23.y};
            #pragma unroll
            for (int jq = 0; jq < SN / 4; jq++) {
                float4 bv = *(const float4*)&bs[kk][tc * SN + jq * 4];
                u64 b0 = pack2(bv.x, bv.x);
                u64 b1 = pack2(bv.y, bv.y);
                u64 b2 = pack2(bv.z, bv.z);
                u64 b3 = pack2(bv.w, bv.w);
                #pragma unroll
                for (int p = 0; p < 4; p++) {
                    acc[p][jq * 4 + 0] = ffma2(ap[p], b0, acc[p][jq * 4 + 0]);
                    acc[p][jq * 4 + 1] = ffma2(ap[p], b1, acc[p][jq * 4 + 1]);
                    acc[p][jq * 4 + 2] = ffma2(ap[p], b2, acc[p][jq * 4 + 2]);
                    acc[p][jq * 4 + 3] = ffma2(ap[p], b3, acc[p][jq * 4 + 3]);
                }
            }
        }
        __syncthreads();
    }

    #pragma unroll
    for (int jq = 0; jq < SN / 4; jq++) {
        float4 bb = *(const float4*)&bias[h0 + tc * SN + jq * 4];
        #pragma unroll
        for (int p = 0; p < 4; p++) {
            float2 f0 = unpack2(acc[p][jq * 4 + 0]);
            float2 f1 = unpack2(acc[p][jq * 4 + 1]);
            float2 f2 = unpack2(acc[p][jq * 4 + 2]);
            float2 f3 = unpack2(acc[p][jq * 4 + 3]);
            int row0 = r0 + tr * 8 + 2 * p;
            float4 o0 = make_float4(f0.x + bb.x, f1.x + bb.y, f2.x + bb.z, f3.x + bb.w);
            float4 o1 = make_float4(f0.y + bb.x, f1.y + bb.y, f2.y + bb.z, f3.y + bb.w);
            *(float4*)&C[(size_t)row0 * Hout + h0 + tc * SN + jq * 4] = o0;
            *(float4*)&C[(size_t)(row0 + 1) * Hout + h0 + tc * SN + jq * 4] = o1;
        }
    }
}

// ---------------------------------------------------------------------------
// Split c1 into c_point (l2-normalized; fp32 + tf32 hi) / c_value.
// ---------------------------------------------------------------------------
__global__ __launch_bounds__(256) void center_norm_kernel()
{
    int w    = (blockIdx.x * blockDim.x + threadIdx.x) >> 5;
    int lane = threadIdx.x & 31;
    int m = w >> 8;
    int s = w & 255;
    int n = m >> 3, f = m & 7;

    const float* row = &g_c1[((size_t)(n * SS + s)) * H2 + f * 64];
    float p = row[lane];
    float v = row[32 + lane];

    float sq = p * p;
    #pragma unroll
    for (int off = 16; off; off >>= 1)
        sq += __shfl_xor_sync(0xffffffffu, sq, off);

    float d = fmaxf(sqrtf(sq), 1e-12f);
    float pn = p / d;
    size_t o = ((size_t)(m * SS + s)) * SCn + lane;
    g_cpHi[o] = f2tf32(pn);
    g_cpF [o] = pn;
    g_cv  [o] = v;
}

// ---------------------------------------------------------------------------
// Fused sim: single tf32-hi MMA pass + certified top-2 gap test.
// Certain rows: exact fp32 recompute of winner only. Uncertain rows
// (gap <= tau): exact fp32 recompute of all 256 sims by the owning warp.
// block = (m, 128-l tile), 256 threads, 8 warps x 16 rows. All 256 s resident.
// ---------------------------------------------------------------------------
__global__ __launch_bounds__(256, 2) void sim_hyb(
    const float* __restrict__ alpha_p, const float* __restrict__ beta_p)
{
    extern __shared__ __align__(16) uint32_t ssm[];
    uint32_t* Ah  = ssm;                           // [128][36] tf32 hi of xn
    float*    Xs  = (float*)(Ah + 128 * 36);       // [128][33] fp32 xn
    uint32_t* Bh  = (uint32_t*)(Xs + 128 * 33);    // [256][36] tf32 hi of cp
    float*    smv = (float*)(Bh + 256 * 36);       // [128]
    int*      sms = (int*)(smv + 128);             // [128]
    int*      sfl = sms + 128;                     // [128]

    const int m  = blockIdx.y;
    const int n  = m >> 3, f = m & 7;
    const int l0 = blockIdx.x * 128;
    const int tid  = threadIdx.x;
    const int wid  = tid >> 5;
    const int lane = tid & 31;
    const int g  = lane >> 2;
    const int tg = lane & 3;

    // prep A: load, l2-normalize, store fp32 + tf32 hi
    #pragma unroll 4
    for (int i = 0; i < 16; i++) {
        int row = wid * 16 + i;
        float x = g_x0p[((size_t)(n * LL + l0 + row)) * HH + f * SCn + lane];
        float sq = x * x;
        #pragma unroll
        for (int off = 16; off; off >>= 1)
            sq += __shfl_xor_sync(0xffffffffu, sq, off);
        float xn = x / fmaxf(sqrtf(sq), 1e-12f);
        Xs[row * 33 + lane] = xn;
        Ah[row * 36 + lane] = f2tf32(xn);
    }
    // prep B: all 256 centers (tf32 hi)
    const uint32_t* cph = &g_cpHi[(size_t)m * SS * SCn];
    #pragma unroll
    for (int it = 0; it < 32; it++) {
        int idx = tid + it * 256;
        Bh[(idx >> 5) * 36 + (idx & 31)] = cph[idx];
    }
    __syncthreads();

    const float alpha = alpha_p[0];
    const float beta  = beta_p[0];

    // A fragments in registers (reused across all 4 s-chunks)
    uint32_t ah[4][4];
    #pragma unroll
    for (int ks = 0; ks < 4; ks++) {
        uint32_t rb = (wid * 16 + g) * 36 + ks * 8 + tg;
        ah[ks][0] = Ah[rb];
        ah[ks][1] = Ah[rb + 8 * 36];
        ah[ks][2] = Ah[rb + 4];
        ah[ks][3] = Ah[rb + 8 * 36 + 4];
    }

    // running top-2 per owned row (r=0: row g, r=1: row g+8)
    float v1[2] = {-INFINITY, -INFINITY};
    float v2[2] = {-INFINITY, -INFINITY};
    int   s1[2] = {0, 0};

    #pragma unroll 1
    for (int cq = 0; cq < 4; cq++) {
        float4 acc[8];
        #pragma unroll
        for (int j = 0; j < 8; j++) acc[j] = make_float4(0.f, 0.f, 0.f, 0.f);

        #pragma unroll
        for (int ks = 0; ks < 4; ks++) {
            #pragma unroll
            for (int j = 0; j < 8; j++) {
                uint32_t rb2 = (cq * 64 + j * 8 + g) * 36 + ks * 8 + tg;
                uint32_t bh[2] = {Bh[rb2], Bh[rb2 + 4]};
                mma8(acc[j], ah[ks], bh);
            }
        }

        // affine + top-2 scan (ascending s, strict >)
        #pragma unroll
        for (int j = 0; j < 8; j++) {
            int s0 = cq * 64 + j * 8 + 2 * tg;
            float vv[4] = {fmaf(alpha, acc[j].x, beta), fmaf(alpha, acc[j].y, beta),
                           fmaf(alpha, acc[j].z, beta), fmaf(alpha, acc[j].w, beta)};
            #pragma unroll
            for (int t = 0; t < 2; t++) {
                int r = t;  // r=0 -> (x,y), r=1 -> (z,w)
                float a0 = vv[2 * t], a1 = vv[2 * t + 1];
                if (a0 > v1[r]) { v2[r] = v1[r]; v1[r] = a0; s1[r] = s0; }
                else if (a0 > v2[r]) v2[r] = a0;
                if (a1 > v1[r]) { v2[r] = v1[r]; v1[r] = a1; s1[r] = s0 + 1; }
                else if (a1 > v2[r]) v2[r] = a1;
            }
        }
    }

    // quad merge (lanes tg 0..3 share rows g/g+8)
    #pragma unroll
    for (int off = 1; off < 4; off <<= 1) {
        #pragma unroll
        for (int r = 0; r < 2; r++) {
            float v1o = __shfl_xor_sync(0xffffffffu, v1[r], off);
            int   s1o = __shfl_xor_sync(0xffffffffu, s1[r], off);
            float v2o = __shfl_xor_sync(0xffffffffu, v2[r], off);
            if (v1o > v1[r]) {
                v2[r] = fmaxf(v1[r], v2o);
                v1[r] = v1o; s1[r] = s1o;
            } else if (v1o < v1[r]) {
                v2[r] = fmaxf(v2[r], v1o);
            } else {  // exact tie across distinct s -> force refine
                if (s1o < s1[r]) s1[r] = s1o;
                v2[r] = v1[r];
            }
        }
    }

    const float tau = fabsf(alpha) * 3e-3f + 1e-6f;
    if (tg == 0) {
        #pragma unroll
        for (int r = 0; r < 2; r++) {
            int row = wid * 16 + g + r * 8;
            sms[row] = s1[r];
            sfl[row] = (v1[r] - v2[r] <= tau) ? 1 : 0;
        }
    }
    __syncwarp();

    // refinement (rows owned by this warp)
    const float* cpF = &g_cpF[(size_t)m * SS * SCn];
    #pragma unroll 1
    for (int i = 0; i < 16; i++) {
        int row = wid * 16 + i;
        int sbest = sms[row];
        float simv;
        if (!sfl[row]) {
            // certain: exact fp32 value of the winner
            float p = Xs[row * 33 + lane] * __ldg(&cpF[sbest * SCn + lane]);
            #pragma unroll
            for (int off = 16; off; off >>= 1)
                p += __shfl_xor_sync(0xffffffffu, p, off);
            simv = p;
        } else {
            // uncertain: exact fp32 over all 256 s; lane l owns s in [8l, 8l+8)
            float bv = -INFINITY, bd = 0.f;
            int bs = 0;
            #pragma unroll 1
            for (int t = 0; t < 8; t++) {
                int s = lane * 8 + t;
                float d = 0.f;
                #pragma unroll
                for (int k = 0; k < 32; k++)
                    d = fmaf(Xs[row * 33 + k], __ldg(&cpF[s * SCn + k]), d);
                float v = fmaf(alpha, d, beta);
                if (v > bv) { bv = v; bs = s; bd = d; }
            }
            #pragma unroll
            for (int off = 16; off; off >>= 1) {
                float vo = __shfl_xor_sync(0xffffffffu, bv, off);
                int   so = __shfl_xor_sync(0xffffffffu, bs, off);
                float d2 = __shfl_xor_sync(0xffffffffu, bd, off);
                if (vo > bv || (vo == bv && so < bs)) { bv = vo; bs = so; bd = d2; }
            }
            simv = bd;
            sbest = bs;
        }
        float sg = 1.f / (1.f + __expf(-fmaf(alpha, simv, beta)));
        if (lane == 0) { smv[row] = sg; sms[row] = sbest; }
    }
    __syncthreads();

    // gather + scale + write dispatched (coalesced)
    const float* cvm = &g_cv[(size_t)m * SS * SCn];
    #pragma unroll
    for (int it = 0; it < 16; it++) {
        int idx = tid + it * 256;
        int row = idx >> 5, k = idx & 31;
        float out = smv[row] * __ldg(&cvm[sms[row] * SCn + k]);
        g_disp[((size_t)(n * LL + l0 + row)) * HH + f * SCn + k] = out;
    }
}

// ---------------------------------------------------------------------------
extern "C" void kernel_launch(void* const* d_in, const int* in_sizes, int n_in,
                              void* d_out, int out_size)
{
    const float* x0      = (const float*)d_in[0];
    const float* center1 = (const float*)d_in[1];
    const float* W0      = (const float*)d_in[2];
    const float* b0      = (const float*)d_in[3];
    const float* W1      = (const float*)d_in[4];
    const float* b1      = (const float*)d_in[5];
    const float* Wm      = (const float*)d_in[6];
    const float* bm      = (const float*)d_in[7];
    const float* alpha   = (const float*)d_in[8];
    const float* beta    = (const float*)d_in[9];
    float* out           = (float*)d_out;

    float* c1p;   cudaGetSymbolAddress((void**)&c1p,  g_c1);
    float* x0pp;  cudaGetSymbolAddress((void**)&x0pp, g_x0p);
    float* dispp; cudaGetSymbolAddress((void**)&dispp, g_disp);

    const int simSmem  = (128 * 36 + 128 * 33 + 256 * 36) * 4 + 128 * 12;  // 73728
    const int mma3Smem = (4608 * 2 + 2304 * 2) * 4;                        // 55296
    const int mma1Smem = (4608 + 2304) * 4;                                // 27648
    cudaFuncSetAttribute(sim_hyb, cudaFuncAttributeMaxDynamicSharedMemorySize, simSmem);
    cudaFuncSetAttribute(gemm_mma<3>, cudaFuncAttributeMaxDynamicSharedMemorySize, mma3Smem);
    cudaFuncSetAttribute(gemm_mma<1>, cudaFuncAttributeMaxDynamicSharedMemorySize, mma1Smem);

    // K1: c1 = center1 @ W1^T + b1   (1024 x 512 x 256), fp32 FFMA2
    gemm_nt<64><<<dim3(1024 / 128, H2 / 64), 256>>>(center1, W1, b1, c1p, H2);

    // K1b: normalize c_point (fp32 + tf32 hi), split c_value
    center_norm_kernel<<<1024, 256>>>();

    // K2: x0p = x0 @ W0^T + b0  (3xTF32 mma.sync — fp32-accurate)
    gemm_mma<3><<<dim3((NB * LL) / 128, HH / 64), 256, mma3Smem>>>(x0, W0, b0, x0pp, HH);

    // K3: sim hi-pass + certified refine + sigmoid + gather -> dispatched
    sim_hyb<<<dim3(LL / 128, MM), 256, simSmem>>>(alpha, beta);

    // K4: out = dispatched @ Wm^T + bm  (single-pass tf32 mma.sync)
    gemm_mma<1><<<dim3((NB * LL) / 128, HH / 64), 256, mma1Smem>>>(dispp, Wm, bm, out, HH);
}

// round 9
// speedup vs baseline: 3.3308x; 3.3308x over previous
#include <cuda_runtime.h>
#include <math.h>
#include <stdint.h>

// Problem constants
#define NB   4
#define LL   4096
#define SS   256
#define HH   256
#define FCn  8
#define SCn  32
#define MM   32      // NB*FCn
#define H2   512
#define KK   256     // inner dim of dense GEMMs

typedef unsigned long long u64;

// Scratch (device globals; no dynamic allocation allowed)
__device__ float    g_c1[NB * SS * H2];       // center1 @ W1^T + b1
__device__ uint32_t g_cpHi[MM * SS * SCn];    // tf32 hi of normalized c_point
__device__ uint32_t g_cpLo[MM * SS * SCn];    // tf32 lo residual
__device__ float    g_cv  [MM * SS * SCn];    // c_value
__device__ float    g_x0p [NB * LL * HH];     // x0 @ W0^T + b0
__device__ float    g_disp[NB * LL * HH];     // dispatched

// ---------------------------------------------------------------------------
// PTX helpers
// ---------------------------------------------------------------------------
__device__ __forceinline__ u64 ffma2(u64 a, u64 b, u64 c) {
    u64 d;
    asm("fma.rn.f32x2 %0, %1, %2, %3;" : "=l"(d) : "l"(a), "l"(b), "l"(c));
    return d;
}
__device__ __forceinline__ u64 pack2(float x, float y) {
    u64 r;
    asm("mov.b64 %0, {%1, %2};" : "=l"(r) : "f"(x), "f"(y));
    return r;
}
__device__ __forceinline__ float2 unpack2(u64 v) {
    float2 f;
    asm("mov.b64 {%0, %1}, %2;" : "=f"(f.x), "=f"(f.y) : "l"(v));
    return f;
}
__device__ __forceinline__ uint32_t f2tf32(float x) {
    uint32_t r;
    asm("cvt.rna.tf32.f32 %0, %1;" : "=r"(r) : "f"(x));
    return r;
}
// m16n8k8 tf32 warp MMA, D += A*B (fp32 accum)
__device__ __forceinline__ void mma8(float4& d, const uint32_t* a, const uint32_t* b) {
    asm("mma.sync.aligned.m16n8k8.row.col.f32.tf32.tf32.f32 "
        "{%0,%1,%2,%3}, {%4,%5,%6,%7}, {%8,%9}, {%0,%1,%2,%3};"
        : "+f"(d.x), "+f"(d.y), "+f"(d.z), "+f"(d.w)
        : "r"(a[0]), "r"(a[1]), "r"(a[2]), "r"(a[3]), "r"(b[0]), "r"(b[1]));
}

// ---------------------------------------------------------------------------
// Tensor-core GEMM via mma.sync tf32 (block tile 128x128, one full wave):
//   C[R][Hout] = A[R][256] @ B[Hout][256]^T + bias
// NPASS=1: plain tf32 — K4.  NPASS=3: hi/lo compensation (~fp32) — K2.
// 8 warps: 4m x 2n; warp tile 32m x 64n (2x8 m16n8 tiles).
// ---------------------------------------------------------------------------
template<int NPASS>
__global__ __launch_bounds__(256, 2) void gemm_mma(
    const float* __restrict__ A, const float* __restrict__ B,
    const float* __restrict__ bias, float* __restrict__ C, int Hout)
{
    extern __shared__ __align__(16) uint32_t msm[];
    uint32_t* Ah = msm;                                    // [128][36]
    uint32_t* Al = Ah + 4608;                              // NPASS==3 only
    uint32_t* Bh = (NPASS == 3) ? (Al + 4608) : (Ah + 4608);  // [128][36]
    uint32_t* Bl = Bh + 4608;                              // NPASS==3 only

    const int tid  = threadIdx.x;
    const int wid  = tid >> 5;
    const int lane = tid & 31;
    const int g  = lane >> 2;
    const int tg = lane & 3;
    const int mbase = (wid & 3) * 32;
    const int nbase = (wid >> 2) * 64;
    const int r0 = blockIdx.x * 128;
    const int h0 = blockIdx.y * 128;

    float4 acc[2][8];
    #pragma unroll
    for (int i = 0; i < 2; i++)
        #pragma unroll
        for (int j = 0; j < 8; j++) acc[i][j] = make_float4(0.f, 0.f, 0.f, 0.f);

    for (int c = 0; c < 8; c++) {
        __syncthreads();
        #pragma unroll
        for (int it = 0; it < 4; it++) {
            int idx = tid + it * 256;
            int row = idx >> 3, j = idx & 7;
            float4 v = *(const float4*)&A[(size_t)(r0 + row) * 256 + c * 32 + j * 4];
            uint32_t base = row * 36 + j * 4;
            float xs[4] = {v.x, v.y, v.z, v.w};
            #pragma unroll
            for (int t = 0; t < 4; t++) {
                uint32_t hi = f2tf32(xs[t]);
                Ah[base + t] = hi;
                if constexpr (NPASS == 3)
                    Al[base + t] = f2tf32(xs[t] - __uint_as_float(hi));
            }
        }
        #pragma unroll
        for (int it = 0; it < 4; it++) {
            int idx = tid + it * 256;
            int row = idx >> 3, j = idx & 7;
            float4 v = *(const float4*)&B[(size_t)(h0 + row) * 256 + c * 32 + j * 4];
            uint32_t base = row * 36 + j * 4;
            float xs[4] = {v.x, v.y, v.z, v.w};
            #pragma unroll
            for (int t = 0; t < 4; t++) {
                uint32_t hi = f2tf32(xs[t]);
                Bh[base + t] = hi;
                if constexpr (NPASS == 3)
                    Bl[base + t] = f2tf32(xs[t] - __uint_as_float(hi));
            }
        }
        __syncthreads();

        #pragma unroll
        for (int ks = 0; ks < 4; ks++) {
            const int k0 = ks * 8;
            uint32_t ah[2][4], al[2][4];
            #pragma unroll
            for (int i = 0; i < 2; i++) {
                uint32_t rb = (mbase + i * 16 + g) * 36 + k0 + tg;
                ah[i][0] = Ah[rb];
                ah[i][1] = Ah[rb + 8 * 36];
                ah[i][2] = Ah[rb + 4];
                ah[i][3] = Ah[rb + 8 * 36 + 4];
                if constexpr (NPASS == 3) {
                    al[i][0] = Al[rb];
                    al[i][1] = Al[rb + 8 * 36];
                    al[i][2] = Al[rb + 4];
                    al[i][3] = Al[rb + 8 * 36 + 4];
                }
            }
            #pragma unroll
            for (int j = 0; j < 8; j++) {
                uint32_t rb = (nbase + j * 8 + g) * 36 + k0 + tg;
                uint32_t bh[2] = {Bh[rb], Bh[rb + 4]};
                #pragma unroll
                for (int i = 0; i < 2; i++)
                    mma8(acc[i][j], ah[i], bh);
                if constexpr (NPASS == 3) {
                    uint32_t bl[2] = {Bl[rb], Bl[rb + 4]};
                    #pragma unroll
                    for (int i = 0; i < 2; i++) {
                        mma8(acc[i][j], ah[i], bl);
                        mma8(acc[i][j], al[i], bh);
                    }
                }
            }
        }
    }

    #pragma unroll
    for (int j = 0; j < 8; j++) {
        int col = h0 + nbase + j * 8 + 2 * tg;
        float2 bb = *(const float2*)&bias[col];
        #pragma unroll
        for (int i = 0; i < 2; i++) {
            int row = r0 + mbase + i * 16 + g;
            float2 o0 = make_float2(acc[i][j].x + bb.x, acc[i][j].y + bb.y);
            float2 o1 = make_float2(acc[i][j].z + bb.x, acc[i][j].w + bb.y);
            *(float2*)&C[(size_t)row * Hout + col] = o0;
            *(float2*)&C[(size_t)(row + 8) * Hout + col] = o1;
        }
    }
}

// ---------------------------------------------------------------------------
// Dense fp32 GEMM (K1 only)
// ---------------------------------------------------------------------------
template<int NT>
__global__ __launch_bounds__(256, 2) void gemm_nt(
    const float* __restrict__ A, const float* __restrict__ B,
    const float* __restrict__ bias, float* __restrict__ C, int Hout)
{
    constexpr int SN = NT / 16;
    __shared__ __align__(16) float as[32][132];
    __shared__ __align__(16) float bs[32][NT + 4];

    const int r0 = blockIdx.x * 128;
    const int h0 = blockIdx.y * NT;
    const int tid = threadIdx.x;
    const int tc = tid & 15;
    const int tr = tid >> 4;
    const int k4 = (tid & 7) * 4;
    const int rl = tid >> 3;

    u64 acc[4][SN];
    #pragma unroll
    for (int p = 0; p < 4; p++)
        #pragma unroll
        for (int j = 0; j < SN; j++) acc[p][j] = 0ull;

    for (int k0 = 0; k0 < KK; k0 += 32) {
        #pragma unroll
        for (int it = 0; it < 4; it++) {
            int row = rl + it * 32;
            float4 v = *(const float4*)&A[(size_t)(r0 + row) * KK + k0 + k4];
            as[k4 + 0][row] = v.x;
            as[k4 + 1][row] = v.y;
            as[k4 + 2][row] = v.z;
            as[k4 + 3][row] = v.w;
        }
        #pragma unroll
        for (int it = 0; it < NT / 32; it++) {
            int h = rl + it * 32;
            float4 v = *(const float4*)&B[(size_t)(h0 + h) * KK + k0 + k4];
            bs[k4 + 0][h] = v.x;
            bs[k4 + 1][h] = v.y;
            bs[k4 + 2][h] = v.z;
            bs[k4 + 3][h] = v.w;
        }
        __syncthreads();

        #pragma unroll 8
        for (int kk = 0; kk < 32; kk++) {
            ulonglong2 a01 = *(const ulonglong2*)&as[kk][tr * 8];
            ulonglong2 a23 = *(const ulonglong2*)&as[kk][tr * 8 + 4];
            u64 ap[4] = {a01.x, a01.y, a23.x, a23.y};
            #pragma unroll
            for (int jq = 0; jq < SN / 4; jq++) {
                float4 bv = *(const float4*)&bs[kk][tc * SN + jq * 4];
                u64 b0 = pack2(bv.x, bv.x);
                u64 b1 = pack2(bv.y, bv.y);
                u64 b2 = pack2(bv.z, bv.z);
                u64 b3 = pack2(bv.w, bv.w);
                #pragma unroll
                for (int p = 0; p < 4; p++) {
                    acc[p][jq * 4 + 0] = ffma2(ap[p], b0, acc[p][jq * 4 + 0]);
                    acc[p][jq * 4 + 1] = ffma2(ap[p], b1, acc[p][jq * 4 + 1]);
                    acc[p][jq * 4 + 2] = ffma2(ap[p], b2, acc[p][jq * 4 + 2]);
                    acc[p][jq * 4 + 3] = ffma2(ap[p], b3, acc[p][jq * 4 + 3]);
                }
            }
        }
        __syncthreads();
    }

    #pragma unroll
    for (int jq = 0; jq < SN / 4; jq++) {
        float4 bb = *(const float4*)&bias[h0 + tc * SN + jq * 4];
        #pragma unroll
        for (int p = 0; p < 4; p++) {
            float2 f0 = unpack2(acc[p][jq * 4 + 0]);
            float2 f1 = unpack2(acc[p][jq * 4 + 1]);
            float2 f2 = unpack2(acc[p][jq * 4 + 2]);
            float2 f3 = unpack2(acc[p][jq * 4 + 3]);
            int row0 = r0 + tr * 8 + 2 * p;
            float4 o0 = make_float4(f0.x + bb.x, f1.x + bb.y, f2.x + bb.z, f3.x + bb.w);
            float4 o1 = make_float4(f0.y + bb.x, f1.y + bb.y, f2.y + bb.z, f3.y + bb.w);
            *(float4*)&C[(size_t)row0 * Hout + h0 + tc * SN + jq * 4] = o0;
            *(float4*)&C[(size_t)(row0 + 1) * Hout + h0 + tc * SN + jq * 4] = o1;
        }
    }
}

// ---------------------------------------------------------------------------
// Split c1 into c_point (l2-normalized, tf32 hi/lo split) / c_value.
// ---------------------------------------------------------------------------
__global__ __launch_bounds__(256) void center_norm_kernel()
{
    int w    = (blockIdx.x * blockDim.x + threadIdx.x) >> 5;
    int lane = threadIdx.x & 31;
    int m = w >> 8;
    int s = w & 255;
    int n = m >> 3, f = m & 7;

    const float* row = &g_c1[((size_t)(n * SS + s)) * H2 + f * 64];
    float p = row[lane];
    float v = row[32 + lane];

    float sq = p * p;
    #pragma unroll
    for (int off = 16; off; off >>= 1)
        sq += __shfl_xor_sync(0xffffffffu, sq, off);

    float d = fmaxf(sqrtf(sq), 1e-12f);
    float pn = p / d;
    size_t o = ((size_t)(m * SS + s)) * SCn + lane;
    uint32_t hi = f2tf32(pn);
    g_cpHi[o] = hi;
    g_cpLo[o] = f2tf32(pn - __uint_as_float(hi));
    g_cv [o] = v;
}

// ---------------------------------------------------------------------------
// Fused sim (3xTF32 mma.sync) + argmax + sigmoid + gather.
// All 256 centers resident (hi+lo), one barrier, A-hi fragments in registers.
// block = (m, 128-l tile), 256 threads, 8 warps x 16 rows.
// ---------------------------------------------------------------------------
__global__ __launch_bounds__(256, 2) void sim_mma(
    const float* __restrict__ alpha_p, const float* __restrict__ beta_p)
{
    extern __shared__ __align__(16) uint32_t ssm[];
    uint32_t* Ah = ssm;                 // [128][36]
    uint32_t* Al = Ah + 128 * 36;
    uint32_t* Bh = Al + 128 * 36;       // [256][36]
    uint32_t* Bl = Bh + 256 * 36;
    float*    smv = (float*)(Bl + 256 * 36);   // [128]
    int*      sms = (int*)(smv + 128);         // [128]

    const int m  = blockIdx.y;
    const int n  = m >> 3, f = m & 7;
    const int l0 = blockIdx.x * 128;
    const int tid  = threadIdx.x;
    const int wid  = tid >> 5;
    const int lane = tid & 31;
    const int g  = lane >> 2;
    const int tg = lane & 3;

    // A: load x0p rows, l2-normalize, tf32 hi/lo split -> smem (stride 36)
    #pragma unroll 4
    for (int i = 0; i < 16; i++) {
        int row = wid * 16 + i;
        float x = g_x0p[((size_t)(n * LL + l0 + row)) * HH + f * SCn + lane];
        float sq = x * x;
        #pragma unroll
        for (int off = 16; off; off >>= 1)
            sq += __shfl_xor_sync(0xffffffffu, sq, off);
        float xn = x / fmaxf(sqrtf(sq), 1e-12f);
        uint32_t hi = f2tf32(xn);
        Ah[row * 36 + lane] = hi;
        Al[row * 36 + lane] = f2tf32(xn - __uint_as_float(hi));
    }

    // B: all 256 centers (hi+lo), conflict-free scalar copies
    const uint32_t* cph = &g_cpHi[(size_t)m * SS * SCn];
    const uint32_t* cpl = &g_cpLo[(size_t)m * SS * SCn];
    #pragma unroll
    for (int it = 0; it < 32; it++) {
        int idx = tid + it * 256;
        int srow = idx >> 5, k = idx & 31;
        Bh[srow * 36 + k] = cph[idx];
        Bl[srow * 36 + k] = cpl[idx];
    }
    __syncthreads();

    const float alpha = alpha_p[0];
    const float beta  = beta_p[0];

    // A-hi fragments hoisted (reused for all 4 s-chunks)
    uint32_t ah[4][4];
    #pragma unroll
    for (int ks = 0; ks < 4; ks++) {
        uint32_t rb = (wid * 16 + g) * 36 + ks * 8 + tg;
        ah[ks][0] = Ah[rb];
        ah[ks][1] = Ah[rb + 8 * 36];
        ah[ks][2] = Ah[rb + 4];
        ah[ks][3] = Ah[rb + 8 * 36 + 4];
    }

    float vb[2] = {-INFINITY, -INFINITY};
    int   sb[2] = {0, 0};

    #pragma unroll 1
    for (int cq = 0; cq < 4; cq++) {
        float4 acc[8];
        #pragma unroll
        for (int j = 0; j < 8; j++) acc[j] = make_float4(0.f, 0.f, 0.f, 0.f);

        #pragma unroll
        for (int ks = 0; ks < 4; ks++) {
            uint32_t rba = (wid * 16 + g) * 36 + ks * 8 + tg;
            uint32_t alo[4] = {Al[rba], Al[rba + 8 * 36], Al[rba + 4], Al[rba + 8 * 36 + 4]};
            #pragma unroll
            for (int j = 0; j < 8; j++) {
                uint32_t rb2 = (cq * 64 + j * 8 + g) * 36 + ks * 8 + tg;
                uint32_t bhh[2] = {Bh[rb2], Bh[rb2 + 4]};
                uint32_t blo[2] = {Bl[rb2], Bl[rb2 + 4]};
                mma8(acc[j], ah[ks], bhh);
                mma8(acc[j], ah[ks], blo);
                mma8(acc[j], alo,    bhh);
            }
        }

        // running affine argmax (ascending s, strict >)
        const int sbase = cq * 64;
        #pragma unroll
        for (int j = 0; j < 8; j++) {
            int s0 = sbase + j * 8 + 2 * tg;
            float v0 = fmaf(alpha, acc[j].x, beta);
            float v1 = fmaf(alpha, acc[j].y, beta);
            float v2 = fmaf(alpha, acc[j].z, beta);
            float v3 = fmaf(alpha, acc[j].w, beta);
            if (v0 > vb[0]) { vb[0] = v0; sb[0] = s0; }
            if (v1 > vb[0]) { vb[0] = v1; sb[0] = s0 + 1; }
            if (v2 > vb[1]) { vb[1] = v2; sb[1] = s0; }
            if (v3 > vb[1]) { vb[1] = v3; sb[1] = s0 + 1; }
        }
    }

    // reduce argmax across the 4 tg-lanes of each quad (rows g / g+8)
    #pragma unroll
    for (int r = 0; r < 2; r++) {
        #pragma unroll
        for (int off = 1; off < 4; off <<= 1) {
            float v2 = __shfl_xor_sync(0xffffffffu, vb[r], off);
            int   s2 = __shfl_xor_sync(0xffffffffu, sb[r], off);
            if (v2 > vb[r] || (v2 == vb[r] && s2 < sb[r])) { vb[r] = v2; sb[r] = s2; }
        }
    }
    if (tg == 0) {
        int row0 = wid * 16 + g;
        smv[row0]     = 1.f / (1.f + __expf(-vb[0]));
        sms[row0]     = sb[0];
        smv[row0 + 8] = 1.f / (1.f + __expf(-vb[1]));
        sms[row0 + 8] = sb[1];
    }
    __syncthreads();

    // gather + scale + write dispatched
    const float* cvm = &g_cv[(size_t)m * SS * SCn];
    #pragma unroll
    for (int it = 0; it < 16; it++) {
        int idx = tid + it * 256;
        int row = idx >> 5, k = idx & 31;
        float out = smv[row] * __ldg(&cvm[sms[row] * SCn + k]);
        g_disp[((size_t)(n * LL + l0 + row)) * HH + f * SCn + k] = out;
    }
}

// ---------------------------------------------------------------------------
extern "C" void kernel_launch(void* const* d_in, const int* in_sizes, int n_in,
                              void* d_out, int out_size)
{
    const float* x0      = (const float*)d_in[0];
    const float* center1 = (const float*)d_in[1];
    const float* W0      = (const float*)d_in[2];
    const float* b0      = (const float*)d_in[3];
    const float* W1      = (const float*)d_in[4];
    const float* b1      = (const float*)d_in[5];
    const float* Wm      = (const float*)d_in[6];
    const float* bm      = (const float*)d_in[7];
    const float* alpha   = (const float*)d_in[8];
    const float* beta    = (const float*)d_in[9];
    float* out           = (float*)d_out;

    float* c1p;   cudaGetSymbolAddress((void**)&c1p,  g_c1);
    float* x0pp;  cudaGetSymbolAddress((void**)&x0pp, g_x0p);
    float* dispp; cudaGetSymbolAddress((void**)&dispp, g_disp);

    const int simSmem  = (2 * 128 * 36 + 2 * 256 * 36) * 4 + 128 * 8;  // 111616
    const int mma3Smem = 4 * 4608 * 4;                                  // 73728
    const int mma1Smem = 2 * 4608 * 4;                                  // 36864
    cudaFuncSetAttribute(sim_mma, cudaFuncAttributeMaxDynamicSharedMemorySize, simSmem);
    cudaFuncSetAttribute(gemm_mma<3>, cudaFuncAttributeMaxDynamicSharedMemorySize, mma3Smem);
    cudaFuncSetAttribute(gemm_mma<1>, cudaFuncAttributeMaxDynamicSharedMemorySize, mma1Smem);

    // K1: c1 = center1 @ W1^T + b1   (1024 x 512 x 256), fp32 FFMA2
    gemm_nt<64><<<dim3(1024 / 128, H2 / 64), 256>>>(center1, W1, b1, c1p, H2);

    // K1b: normalize c_point (tf32 hi/lo split), split c_value
    center_norm_kernel<<<1024, 256>>>();

    // K2: x0p = x0 @ W0^T + b0  (3xTF32 mma.sync, 128x128 tiles, 1 wave)
    gemm_mma<3><<<dim3((NB * LL) / 128, HH / 128), 256, mma3Smem>>>(x0, W0, b0, x0pp, HH);

    // K3: sim (3xTF32 mma.sync) + argmax + sigmoid + gather -> dispatched
    sim_mma<<<dim3(LL / 128, MM), 256, simSmem>>>(alpha, beta);

    // K4: out = dispatched @ Wm^T + bm  (single-pass tf32, 128x128 tiles)
    gemm_mma<1><<<dim3((NB * LL) / 128, HH / 128), 256, mma1Smem>>>(dispp, Wm, bm, out, HH);
}